// round 1
// baseline (speedup 1.0000x reference)
#include <cuda_runtime.h>
#include <math_constants.h>

// Dilate (5x5 per-channel max filter, SAME padding) over (64, 384, 384, 3) fp32.
// Separable: vertical 5-max in registers (streaming window), horizontal 5-max
// via one shared-memory row (double buffered). One LDG.128 in, one STG.128 out
// per float4 -> HBM-bound design.

#define IMG_H 384
#define IMG_W 384
#define IMG_C 3
#define ROWF (IMG_W * IMG_C)   // 1152 floats per row
#define ROWV (ROWF / 4)        // 288 float4 per row
#define TH   32                // output rows per block
#define PADV 2                 // float4 halo pad on each side of smem row

__device__ __forceinline__ float max5f(float a, float b, float c, float d, float e) {
    return fmaxf(fmaxf(fmaxf(a, b), fmaxf(c, d)), e);
}

__device__ __forceinline__ float4 vmax5(float4 a, float4 b, float4 c, float4 d, float4 e) {
    float4 r;
    r.x = max5f(a.x, b.x, c.x, d.x, e.x);
    r.y = max5f(a.y, b.y, c.y, d.y, e.y);
    r.z = max5f(a.z, b.z, c.z, d.z, e.z);
    r.w = max5f(a.w, b.w, c.w, d.w, e.w);
    return r;
}

__global__ void __launch_bounds__(ROWV, 3)
dilate5_kernel(const float* __restrict__ in, float* __restrict__ out) {
    // Two row buffers, each padded by 2 float4 (8 floats) on both sides.
    __shared__ __align__(16) float sbuf[2][(PADV * 4) + ROWF + (PADV * 4)];

    const int t   = threadIdx.x;            // 0..287 float4 column
    const int img = blockIdx.y;
    const int y0  = blockIdx.x * TH;

    const float* base  = in  + (size_t)img * IMG_H * ROWF;
    float*       obase = out + (size_t)img * IMG_H * ROWF;

    auto loadrow = [&](int y) -> float4 {
        y = min(max(y, 0), IMG_H - 1);
        return __ldg(reinterpret_cast<const float4*>(base + (size_t)y * ROWF) + t);
    };

    // Rolling vertical window: rows y-2 .. y+2 (clamped).
    float4 w0 = loadrow(y0 - 2);
    float4 w1 = loadrow(y0 - 1);
    float4 w2 = loadrow(y0);
    float4 w3 = loadrow(y0 + 1);
    float4 w4 = loadrow(y0 + 2);

    const bool interior = (t >= 2) && (t < ROWV - 2);

    for (int i = 0; i < TH; ++i) {
        const int y = y0 + i;

        // Vertical 5-tap max for this thread's float4 column.
        const float4 v = vmax5(w0, w1, w2, w3, w4);

        float* srow = sbuf[i & 1] + PADV * 4;   // points at float index 0 of row
        reinterpret_cast<float4*>(srow)[t] = v; // 32B-offset base -> 16B aligned
        __syncthreads();

        // Horizontal 5-tap max, tap stride = 3 floats (channel interleave).
        float4 o;
        if (interior) {
            const float4* sv = reinterpret_cast<const float4*>(srow);
            const float4 a = sv[t - 2];
            const float4 b = sv[t - 1];
            const float4 c = v;          // own column from register
            const float4 d = sv[t + 1];
            const float4 e = sv[t + 2];
            // float index j = 4t + f; taps at j-6, j-3, j, j+3, j+6
            o.x = max5f(a.z, b.y, c.x, c.w, d.z);
            o.y = max5f(a.w, b.z, c.y, d.x, d.w);
            o.z = max5f(b.x, b.w, c.z, d.y, e.x);
            o.w = max5f(b.y, c.x, c.w, d.z, e.y);
        } else {
            // Edge columns: scalar path with per-pixel clamping.
            float r[4];
            #pragma unroll
            for (int f = 0; f < 4; ++f) {
                const int j  = 4 * t + f;
                const int x  = j / 3;
                const int ch = j - 3 * x;
                float m = -CUDART_INF_F;
                #pragma unroll
                for (int d2 = -2; d2 <= 2; ++d2) {
                    const int xx = min(max(x + d2, 0), IMG_W - 1);
                    m = fmaxf(m, srow[xx * 3 + ch]);
                }
                r[f] = m;
            }
            o = make_float4(r[0], r[1], r[2], r[3]);
        }

        reinterpret_cast<float4*>(obase + (size_t)y * ROWF)[t] = o;

        // Shift window down one row.
        w0 = w1; w1 = w2; w2 = w3; w3 = w4;
        w4 = loadrow(y + 3);
    }
}

extern "C" void kernel_launch(void* const* d_in, const int* in_sizes, int n_in,
                              void* d_out, int out_size) {
    (void)in_sizes; (void)n_in; (void)out_size;
    const float* images = (const float*)d_in[0];
    // d_in[1] is k (always 5 for this problem's fixed setup)
    float* out = (float*)d_out;

    dim3 grid(IMG_H / TH, 64);
    dim3 block(ROWV);
    dilate5_kernel<<<grid, block>>>(images, out);
}

// round 2
// speedup vs baseline: 1.2649x; 1.2649x over previous
#include <cuda_runtime.h>
#include <math_constants.h>

// Dilate (5x5 per-channel max filter, SAME padding) over (64, 384, 384, 3) fp32.
// Separable: vertical 5-max on a rolling 8-row register window (4 rows/batch,
// MLP=4 prefetch one full batch ahead), horizontal 5-max from a double-buffered
// shared row group. One LDG.128 in + one STG.128 out per float4.

#define IMG_H 384
#define IMG_W 384
#define IMG_C 3
#define ROWF (IMG_W * IMG_C)   // 1152 floats per row
#define ROWV (ROWF / 4)        // 288 float4 per row
#define TH   48                // output rows per block
#define U    4                 // rows per batch (one barrier per batch)

__device__ __forceinline__ float max5f(float a, float b, float c, float d, float e) {
    return fmaxf(fmaxf(fmaxf(a, b), fmaxf(c, d)), e);
}

__device__ __forceinline__ float4 vmax5(float4 a, float4 b, float4 c, float4 d, float4 e) {
    float4 r;
    r.x = max5f(a.x, b.x, c.x, d.x, e.x);
    r.y = max5f(a.y, b.y, c.y, d.y, e.y);
    r.z = max5f(a.z, b.z, c.z, d.z, e.z);
    r.w = max5f(a.w, b.w, c.w, d.w, e.w);
    return r;
}

__global__ void __launch_bounds__(ROWV, 3)
dilate5_kernel(const float* __restrict__ in, float* __restrict__ out) {
    // Double-buffered group of U vertical-max rows. 2*4*288*16B = 36,864B.
    __shared__ __align__(16) float4 sbuf[2][U][ROWV];

    const int t   = threadIdx.x;            // float4 column 0..287
    const int img = blockIdx.y;
    const int y0  = blockIdx.x * TH;

    const float* base  = in  + (size_t)img * IMG_H * ROWF;
    float*       obase = out + (size_t)img * IMG_H * ROWF;

    auto loadrow = [&](int y) -> float4 {
        y = min(max(y, 0), IMG_H - 1);
        return __ldg(reinterpret_cast<const float4*>(base + (size_t)y * ROWF) + t);
    };

    // Rolling window of U+4 = 8 input rows: rows (y0+i-2) .. (y0+i+5).
    float4 r[U + 4];
    #pragma unroll
    for (int j = 0; j < U + 4; ++j) r[j] = loadrow(y0 - 2 + j);

    const bool interior = (t >= 2) && (t < ROWV - 2);
    int buf = 0;

    for (int i = 0; i < TH; i += U) {
        // Vertical 5-tap max for U consecutive output rows -> smem.
        #pragma unroll
        for (int j = 0; j < U; ++j)
            sbuf[buf][j][t] = vmax5(r[j], r[j + 1], r[j + 2], r[j + 3], r[j + 4]);
        __syncthreads();

        // Shift the window and issue next batch of loads NOW; they are consumed
        // only on the next outer iteration -> DRAM latency overlapped with the
        // horizontal pass below (which reads smem only).
        #pragma unroll
        for (int j = 0; j < 4; ++j) r[j] = r[j + U];
        #pragma unroll
        for (int j = 0; j < U; ++j) r[4 + j] = loadrow(y0 + i + U + 2 + j);

        // Horizontal 5-tap max (tap stride = 3 floats, channel interleave).
        #pragma unroll
        for (int j = 0; j < U; ++j) {
            const float4* sv = &sbuf[buf][j][0];
            float4 o;
            if (interior) {
                const float4 a = sv[t - 2];
                const float4 b = sv[t - 1];
                const float4 c = sv[t];
                const float4 d = sv[t + 1];
                const float4 e = sv[t + 2];
                // float index jj = 4t+f; taps at jj-6, jj-3, jj, jj+3, jj+6
                o.x = max5f(a.z, b.y, c.x, c.w, d.z);
                o.y = max5f(a.w, b.z, c.y, d.x, d.w);
                o.z = max5f(b.x, b.w, c.z, d.y, e.x);
                o.w = max5f(b.y, c.x, c.w, d.z, e.y);
            } else {
                // Edge columns: scalar path with per-pixel clamping.
                const float* srow = reinterpret_cast<const float*>(sv);
                float rr[4];
                #pragma unroll
                for (int f = 0; f < 4; ++f) {
                    const int jj = 4 * t + f;
                    const int x  = jj / 3;
                    const int ch = jj - 3 * x;
                    float m = -CUDART_INF_F;
                    #pragma unroll
                    for (int d2 = -2; d2 <= 2; ++d2) {
                        const int xx = min(max(x + d2, 0), IMG_W - 1);
                        m = fmaxf(m, srow[xx * 3 + ch]);
                    }
                    rr[f] = m;
                }
                o = make_float4(rr[0], rr[1], rr[2], rr[3]);
            }
            reinterpret_cast<float4*>(obase + (size_t)(y0 + i + j) * ROWF)[t] = o;
        }

        buf ^= 1;
    }
}

extern "C" void kernel_launch(void* const* d_in, const int* in_sizes, int n_in,
                              void* d_out, int out_size) {
    (void)in_sizes; (void)n_in; (void)out_size;
    const float* images = (const float*)d_in[0];
    // d_in[1] is k (fixed at 5 for this problem)
    float* out = (float*)d_out;

    dim3 grid(IMG_H / TH, 64);
    dim3 block(ROWV);
    dilate5_kernel<<<grid, block>>>(images, out);
}

// round 3
// speedup vs baseline: 1.6409x; 1.2973x over previous
#include <cuda_runtime.h>
#include <math_constants.h>

// Dilate (5x5 per-channel max filter, SAME padding) over (64, 384, 384, 3) fp32.
// Separable: vertical 5-max on a rolling 8-row register window (4 rows/batch),
// horizontal 5-max from a double-buffered shared row group.
// R3 changes: prefetch issued BEFORE the barrier (max load->use distance),
// last-batch prefetch guarded off (kills wasted tail reads), TH=48 -> 32 for
// finer wave granularity (768 blocks vs 444 concurrent slots).

#define IMG_H 384
#define IMG_W 384
#define IMG_C 3
#define ROWF (IMG_W * IMG_C)   // 1152 floats per row
#define ROWV (ROWF / 4)        // 288 float4 per row
#define TH   32                // output rows per block
#define U    4                 // rows per batch (one barrier per batch)

__device__ __forceinline__ float max5f(float a, float b, float c, float d, float e) {
    return fmaxf(fmaxf(fmaxf(a, b), fmaxf(c, d)), e);
}

__device__ __forceinline__ float4 vmax5(float4 a, float4 b, float4 c, float4 d, float4 e) {
    float4 r;
    r.x = max5f(a.x, b.x, c.x, d.x, e.x);
    r.y = max5f(a.y, b.y, c.y, d.y, e.y);
    r.z = max5f(a.z, b.z, c.z, d.z, e.z);
    r.w = max5f(a.w, b.w, c.w, d.w, e.w);
    return r;
}

__global__ void __launch_bounds__(ROWV, 3)
dilate5_kernel(const float* __restrict__ in, float* __restrict__ out) {
    // Double-buffered group of U vertical-max rows. 2*4*288*16B = 36,864B.
    __shared__ __align__(16) float4 sbuf[2][U][ROWV];

    const int t   = threadIdx.x;            // float4 column 0..287
    const int img = blockIdx.y;
    const int y0  = blockIdx.x * TH;

    const float* base  = in  + (size_t)img * IMG_H * ROWF;
    float*       obase = out + (size_t)img * IMG_H * ROWF;

    auto loadrow = [&](int y) -> float4 {
        y = min(max(y, 0), IMG_H - 1);
        return __ldg(reinterpret_cast<const float4*>(base + (size_t)y * ROWF) + t);
    };

    // Rolling window of U+4 = 8 input rows: rows (y0+i-2) .. (y0+i+5).
    float4 r[U + 4];
    #pragma unroll
    for (int j = 0; j < U + 4; ++j) r[j] = loadrow(y0 - 2 + j);

    const bool interior = (t >= 2) && (t < ROWV - 2);
    int buf = 0;

    for (int i = 0; i < TH; i += U) {
        // Vertical 5-tap max for U consecutive output rows -> smem.
        #pragma unroll
        for (int j = 0; j < U; ++j)
            sbuf[buf][j][t] = vmax5(r[j], r[j + 1], r[j + 2], r[j + 3], r[j + 4]);

        // Window shift + prefetch for the NEXT batch, issued BEFORE the
        // barrier: loads are independent of the barrier and are consumed a
        // whole batch later, so DRAM latency overlaps barrier + horizontal.
        #pragma unroll
        for (int j = 0; j < 4; ++j) r[j] = r[j + U];
        if (i + U < TH) {
            #pragma unroll
            for (int j = 0; j < U; ++j) r[4 + j] = loadrow(y0 + i + U + 2 + j);
        }

        __syncthreads();

        // Horizontal 5-tap max (tap stride = 3 floats, channel interleave).
        #pragma unroll
        for (int j = 0; j < U; ++j) {
            const float4* sv = &sbuf[buf][j][0];
            float4 o;
            if (interior) {
                const float4 a = sv[t - 2];
                const float4 b = sv[t - 1];
                const float4 c = sv[t];
                const float4 d = sv[t + 1];
                const float4 e = sv[t + 2];
                // float index jj = 4t+f; taps at jj-6, jj-3, jj, jj+3, jj+6
                o.x = max5f(a.z, b.y, c.x, c.w, d.z);
                o.y = max5f(a.w, b.z, c.y, d.x, d.w);
                o.z = max5f(b.x, b.w, c.z, d.y, e.x);
                o.w = max5f(b.y, c.x, c.w, d.z, e.y);
            } else {
                // Edge columns: scalar path with per-pixel clamping.
                const float* srow = reinterpret_cast<const float*>(sv);
                float rr[4];
                #pragma unroll
                for (int f = 0; f < 4; ++f) {
                    const int jj = 4 * t + f;
                    const int x  = jj / 3;
                    const int ch = jj - 3 * x;
                    float m = -CUDART_INF_F;
                    #pragma unroll
                    for (int d2 = -2; d2 <= 2; ++d2) {
                        const int xx = min(max(x + d2, 0), IMG_W - 1);
                        m = fmaxf(m, srow[xx * 3 + ch]);
                    }
                    rr[f] = m;
                }
                o = make_float4(rr[0], rr[1], rr[2], rr[3]);
            }
            reinterpret_cast<float4*>(obase + (size_t)(y0 + i + j) * ROWF)[t] = o;
        }

        buf ^= 1;
    }
}

extern "C" void kernel_launch(void* const* d_in, const int* in_sizes, int n_in,
                              void* d_out, int out_size) {
    (void)in_sizes; (void)n_in; (void)out_size;
    const float* images = (const float*)d_in[0];
    // d_in[1] is k (fixed at 5 for this problem)
    float* out = (float*)d_out;

    dim3 grid(IMG_H / TH, 64);
    dim3 block(ROWV);
    dilate5_kernel<<<grid, block>>>(images, out);
}